// round 13
// baseline (speedup 1.0000x reference)
#include <cuda_runtime.h>
#include <cuda_fp16.h>
#include <cstdint>

#define NN 8192
#define PP 49
#define FF 256
#define EE 256
#define HH 256
#define SS 128
#define MTOT (NN * PP)  // 401408

// Scratch (no allocations allowed)
__device__ float  g_x2[NN * EE];      // 8 MB
__device__ __half g_w1h[EE * FF];     // 128 KB fp16 W1
__device__ __half g_w2h[EE * HH];     // 128 KB fp16 W2
__device__ float  g_rowsum[NN * FF];  // 8 MB
__device__ float  g_scores[NN];
__device__ float  g_attn[NN];

// ---------------------------------------------------------------------------
// helpers
// ---------------------------------------------------------------------------
__device__ __forceinline__ uint32_t smem_u32(const void* p) {
    uint32_t a;
    asm("{ .reg .u64 t; cvta.to.shared.u64 t, %1; cvt.u32.u64 %0, t; }" : "=r"(a) : "l"(p));
    return a;
}
__device__ __forceinline__ float ftanh(float x) {   // err ~1e-6
    float e = __expf(2.f * x);
    return 1.f - __fdividef(2.f, e + 1.f);
}
__device__ __forceinline__ float tanha(float x) {   // MUFU tanh
    float y;
    asm("tanh.approx.f32 %0, %1;" : "=f"(y) : "f"(x));
    return y;
}

#define LDSM4(r, addr) \
    asm volatile("ldmatrix.sync.aligned.m8n8.x4.shared.b16 {%0,%1,%2,%3}, [%4];" \
        : "=r"((r)[0]), "=r"((r)[1]), "=r"((r)[2]), "=r"((r)[3]) : "r"(addr))

#define MMA16816(c, a, b0v, b1v) \
    asm volatile("mma.sync.aligned.m16n8k16.row.col.f32.f16.f16.f32 " \
        "{%0,%1,%2,%3},{%4,%5,%6,%7},{%8,%9},{%0,%1,%2,%3};" \
        : "+f"((c)[0]), "+f"((c)[1]), "+f"((c)[2]), "+f"((c)[3]) \
        : "r"((a)[0]), "r"((a)[1]), "r"((a)[2]), "r"((a)[3]), "r"(b0v), "r"(b1v))

__device__ __forceinline__ uint32_t pack_h2(float a, float b) {
    __half2 h = __floats2half2_rn(a, b);
    return *(uint32_t*)&h;
}

// ---------------------------------------------------------------------------
// K0: convert W1,W2 -> fp16; zero g_scores.
// ---------------------------------------------------------------------------
__global__ __launch_bounds__(256) void k0_prep(const float* __restrict__ W1,
                                               const float* __restrict__ W2) {
    int i = blockIdx.x * 256 + threadIdx.x;   // 0..65535
    g_w1h[i] = __float2half_rn(W1[i]);
    g_w2h[i] = __float2half_rn(W2[i]);
    if (i < NN) g_scores[i] = 0.f;
}

// ---------------------------------------------------------------------------
// K1M: x2 = tanh(H . W2^T + b2) via fp16 mma (f32 acc).  Adapted from the
// R8 e-split kernel (verified): CTA = 128 rows x 128 e-half, grid (64, 2),
// 256 thr, 8 warps (2m x 4n, warp tile 64x32).  Epilogue writes tanh to g_x2.
// ---------------------------------------------------------------------------
#define M_OFF_B2  0       // 512 B
#define M_OFF_BW  2688    // 128*528 = 67584 -> ends 70272
#define M_OFF_A   70272   // 2 * 128*80 = 20480 -> ends 90752
#define M_A_BUF   10240
#define K1M_SMEM  90752

__global__ __launch_bounds__(256, 2) void k1m_x2(const float* __restrict__ Hm,
                                                 const float* __restrict__ b2) {
    extern __shared__ __align__(16) char smem[];
    float* b2s = (float*)(smem + M_OFF_B2);

    const int tid = threadIdx.x;
    const int w = tid >> 5, lane = tid & 31;
    const int tig = lane & 3, g = lane >> 2;
    const int wm = w >> 2, wn = w & 3;
    const int row0 = blockIdx.x * 128;
    const int e0 = blockIdx.y * 128;

    // prefetch A chunk 0
    const float* Xp = Hm + (size_t)(row0 + (tid >> 1)) * HH + (tid & 1) * 16;
    float4 pr0 = *(const float4*)(Xp + 0);
    float4 pr1 = *(const float4*)(Xp + 4);
    float4 pr2 = *(const float4*)(Xp + 8);
    float4 pr3 = *(const float4*)(Xp + 12);

    // B preload: this e-half of g_w2h (64KB) -> 528B-stride rows
    {
        const uint4* Wp = (const uint4*)(g_w2h + (size_t)e0 * HH);
        for (int i = tid; i < 4096; i += 256) {
            int r = i >> 5, s2 = i & 31;
            *(uint4*)(smem + M_OFF_BW + r * 528 + s2 * 16) = Wp[i];
        }
    }
    if (tid < 128) b2s[tid] = b2[e0 + tid];

    float acc[4][4][4];
#pragma unroll
    for (int mt = 0; mt < 4; mt++)
#pragma unroll
        for (int nt = 0; nt < 4; nt++)
#pragma unroll
            for (int i = 0; i < 4; i++) acc[mt][nt][i] = 0.f;

    const uint32_t sb = smem_u32(smem);
    const int arow = lane & 15, asel = lane >> 4;
    const uint32_t aAddr0 = sb + M_OFF_A + (uint32_t)(wm * 64 + arow) * 80 + asel * 16;
    const int brow = (lane & 7) + ((lane >> 4) << 3), bsel = (lane >> 3) & 1;
    const uint32_t bAddr0 = sb + M_OFF_BW + (uint32_t)(wn * 32 + brow) * 528 + bsel * 16;
    char* stsP = smem + M_OFF_A + (tid >> 1) * 80 + (tid & 1) * 32;

    for (int kc = 0; kc < 8; kc++) {
        const uint32_t bo = (kc & 1) * M_A_BUF;
        {
            uint4 q0, q1;
            q0.x = pack_h2(pr0.x, pr0.y); q0.y = pack_h2(pr0.z, pr0.w);
            q0.z = pack_h2(pr1.x, pr1.y); q0.w = pack_h2(pr1.z, pr1.w);
            q1.x = pack_h2(pr2.x, pr2.y); q1.y = pack_h2(pr2.z, pr2.w);
            q1.z = pack_h2(pr3.x, pr3.y); q1.w = pack_h2(pr3.z, pr3.w);
            *(uint4*)(stsP + bo) = q0;
            *(uint4*)(stsP + bo + 16) = q1;
        }
        __syncthreads();
        if (kc < 7) {
            const float* Xn = Xp + (kc + 1) * 32;
            pr0 = *(const float4*)(Xn + 0);
            pr1 = *(const float4*)(Xn + 4);
            pr2 = *(const float4*)(Xn + 8);
            pr3 = *(const float4*)(Xn + 12);
        }
#pragma unroll
        for (int ks = 0; ks < 2; ks++) {
            uint32_t Ar[4][4], Br[2][4];
#pragma unroll
            for (int mt = 0; mt < 4; mt++)
                LDSM4(Ar[mt], aAddr0 + bo + mt * (16 * 80) + ks * 32);
#pragma unroll
            for (int np = 0; np < 2; np++)
                LDSM4(Br[np], bAddr0 + np * (16 * 528) + kc * 64 + ks * 32);
#pragma unroll
            for (int mt = 0; mt < 4; mt++)
#pragma unroll
                for (int nt = 0; nt < 4; nt++)
                    MMA16816(acc[mt][nt], Ar[mt], Br[nt >> 1][(nt & 1) * 2],
                             Br[nt >> 1][(nt & 1) * 2 + 1]);
        }
    }

    // epilogue: x2 = tanh(acc + b2) -> g_x2 (float2 stores)
    float b0r[4], b1r[4];
#pragma unroll
    for (int nt = 0; nt < 4; nt++) {
        b0r[nt] = b2s[wn * 32 + nt * 8 + tig * 2];
        b1r[nt] = b2s[wn * 32 + nt * 8 + tig * 2 + 1];
    }
#pragma unroll
    for (int mt = 0; mt < 4; mt++) {
        int rA = row0 + wm * 64 + mt * 16 + g;
        int rB = rA + 8;
#pragma unroll
        for (int nt = 0; nt < 4; nt++) {
            int e = e0 + wn * 32 + nt * 8 + tig * 2;
            float2 vA = make_float2(ftanh(acc[mt][nt][0] + b0r[nt]),
                                    ftanh(acc[mt][nt][1] + b1r[nt]));
            float2 vB = make_float2(ftanh(acc[mt][nt][2] + b0r[nt]),
                                    ftanh(acc[mt][nt][3] + b1r[nt]));
            *(float2*)&g_x2[(size_t)rA * EE + e] = vA;
            *(float2*)&g_x2[(size_t)rB * EE + e] = vB;
        }
    }
}

// ---------------------------------------------------------------------------
// K2: R4 verbatim — best measured config (446us).
// ---------------------------------------------------------------------------
#define OFF_B1  0
#define OFF_X2  1024
#define OFF_BW  5248
#define OFF_A   140416
#define A_BUF   10240
#define K2_SMEM 160896

__global__ __launch_bounds__(256, 1) void k2_scores(const float* __restrict__ X,
                                                    const float* __restrict__ b1) {
    extern __shared__ __align__(16) char smem[];
    float* b1s = (float*)(smem + OFF_B1);
    float* x2s = (float*)(smem + OFF_X2);

    const int tid = threadIdx.x;
    const int w = tid >> 5, lane = tid & 31;
    const int tig = lane & 3, g = lane >> 2;
    const int wm = w >> 2, wn = w & 3;
    const int row0 = blockIdx.x * 128;
    const int n0 = row0 / PP;

    const float* Xp = X + (size_t)(row0 + (tid >> 1)) * FF + (tid & 1) * 16;
    float4 pr0 = *(const float4*)(Xp + 0);
    float4 pr1 = *(const float4*)(Xp + 4);
    float4 pr2 = *(const float4*)(Xp + 8);
    float4 pr3 = *(const float4*)(Xp + 12);

    {
        const uint4* Wp = (const uint4*)g_w1h;
        for (int i = tid; i < 8192; i += 256) {
            int r = i >> 5, s2 = i & 31;
            *(uint4*)(smem + OFF_BW + r * 528 + s2 * 16) = Wp[i];
        }
    }
    for (int i = tid; i < 4 * EE; i += 256) {
        int s = i >> 8, e = i & 255;
        int n = n0 + s;
        x2s[s * 260 + e] = (n < NN) ? g_x2[(size_t)n * EE + e] : 0.f;
    }
    if (tid < EE) b1s[tid] = b1[tid];

    float acc[4][8][4];
#pragma unroll
    for (int mt = 0; mt < 4; mt++)
#pragma unroll
        for (int nt = 0; nt < 8; nt++)
#pragma unroll
            for (int i = 0; i < 4; i++) acc[mt][nt][i] = 0.f;

    const uint32_t sb = smem_u32(smem);
    const int arow = lane & 15, asel = lane >> 4;
    const uint32_t aAddr0 = sb + OFF_A + (uint32_t)(wm * 64 + arow) * 80 + asel * 16;
    const int brow = (lane & 7) + ((lane >> 4) << 3), bsel = (lane >> 3) & 1;
    const uint32_t bAddr0 = sb + OFF_BW + (uint32_t)(wn * 64 + brow) * 528 + bsel * 16;
    char* stsP = smem + OFF_A + (tid >> 1) * 80 + (tid & 1) * 32;

    for (int kc = 0; kc < 8; kc++) {
        const uint32_t bo = (kc & 1) * A_BUF;
        {
            uint4 q0, q1;
            q0.x = pack_h2(pr0.x, pr0.y); q0.y = pack_h2(pr0.z, pr0.w);
            q0.z = pack_h2(pr1.x, pr1.y); q0.w = pack_h2(pr1.z, pr1.w);
            q1.x = pack_h2(pr2.x, pr2.y); q1.y = pack_h2(pr2.z, pr2.w);
            q1.z = pack_h2(pr3.x, pr3.y); q1.w = pack_h2(pr3.z, pr3.w);
            *(uint4*)(stsP + bo) = q0;
            *(uint4*)(stsP + bo + 16) = q1;
        }
        __syncthreads();
        if (kc < 7) {
            const float* Xn = Xp + (kc + 1) * 32;
            pr0 = *(const float4*)(Xn + 0);
            pr1 = *(const float4*)(Xn + 4);
            pr2 = *(const float4*)(Xn + 8);
            pr3 = *(const float4*)(Xn + 12);
        }
#pragma unroll
        for (int ks = 0; ks < 2; ks++) {
            uint32_t Ar[4][4], Br[4][4];
#pragma unroll
            for (int mt = 0; mt < 4; mt++)
                LDSM4(Ar[mt], aAddr0 + bo + mt * (16 * 80) + ks * 32);
#pragma unroll
            for (int np = 0; np < 4; np++)
                LDSM4(Br[np], bAddr0 + np * (16 * 528) + kc * 64 + ks * 32);
#pragma unroll
            for (int mt = 0; mt < 4; mt++)
#pragma unroll
                for (int nt = 0; nt < 8; nt++)
                    MMA16816(acc[mt][nt], Ar[mt], Br[nt >> 1][(nt & 1) * 2],
                             Br[nt >> 1][(nt & 1) * 2 + 1]);
        }
    }

    const float inv = 1.f / (float)PP;
    float b0r[8], b1r[8];
#pragma unroll
    for (int nt = 0; nt < 8; nt++) {
        b0r[nt] = b1s[wn * 64 + nt * 8 + tig * 2];
        b1r[nt] = b1s[wn * 64 + nt * 8 + tig * 2 + 1];
    }
#pragma unroll
    for (int mt = 0; mt < 4; mt++) {
        int rA = wm * 64 + mt * 16 + g;
        int rB = rA + 8;
        int nA = (row0 + rA) / PP;
        int nB = (row0 + rB) / PP;
        const float* xA = x2s + (nA - n0) * 260 + wn * 64;
        const float* xB = x2s + (nB - n0) * 260 + wn * 64;
        float sA = 0.f, sB = 0.f;
#pragma unroll
        for (int nt = 0; nt < 8; nt++) {
            int c0 = nt * 8 + tig * 2, c1 = c0 + 1;
            sA += tanha(acc[mt][nt][0] + b0r[nt]) * xA[c0]
                + tanha(acc[mt][nt][1] + b1r[nt]) * xA[c1];
            sB += tanha(acc[mt][nt][2] + b0r[nt]) * xB[c0]
                + tanha(acc[mt][nt][3] + b1r[nt]) * xB[c1];
        }
        sA += __shfl_xor_sync(0xffffffffu, sA, 1);
        sA += __shfl_xor_sync(0xffffffffu, sA, 2);
        sB += __shfl_xor_sync(0xffffffffu, sB, 1);
        sB += __shfl_xor_sync(0xffffffffu, sB, 2);
        if (tig == 0) {
            atomicAdd(&g_scores[nA], sA * inv);
            atomicAdd(&g_scores[nB], sB * inv);
        }
    }
}

// ---------------------------------------------------------------------------
// K4a: PERSISTENT rowsum — 148 CTAs x 128 threads (4K regs/CTA) so it
// co-resides with k2 on every SM (57.9K + 4K < 64K regs) and grinds its
// 63us of DRAM work underneath k2's 446us compute shadow.
// ---------------------------------------------------------------------------
__global__ __launch_bounds__(128) void k4a_rowsum(const float* __restrict__ X) {
    for (int idx = blockIdx.x; idx < NN * 2; idx += gridDim.x) {
        int n = idx >> 1;
        int f = (idx & 1) * 128 + threadIdx.x;
        const float* xp = X + (size_t)n * PP * FF + f;
        float acc = 0.f;
#pragma unroll
        for (int p = 0; p < PP; p++) acc += xp[(size_t)p * FF];
        g_rowsum[(size_t)n * FF + f] = acc;
    }
}

// ---------------------------------------------------------------------------
// K3: per-segment softmax over scalar scores (patch_lens int32 or int64).
// ---------------------------------------------------------------------------
__device__ __forceinline__ int seg_len(const int* p32, int is64, int i) {
    return is64 ? p32[2 * i] : p32[i];
}

__global__ __launch_bounds__(128) void k3_softmax(const int* __restrict__ lens32) {
    __shared__ float sh[128];
    __shared__ int s_off, s_len;
    int s = blockIdx.x, tid = threadIdx.x;
    if (tid == 0) {
        int is64 = (lens32[1] == 0) ? 1 : 0;
        int o = 0;
        for (int i = 0; i < s; i++) o += seg_len(lens32, is64, i);
        s_off = o;
        s_len = seg_len(lens32, is64, s);
    }
    __syncthreads();
    int off = s_off, len = s_len;
    float v = (tid < len) ? g_scores[off + tid] : -1e30f;
    sh[tid] = v;
    __syncthreads();
    for (int st = 64; st > 0; st >>= 1) {
        if (tid < st) sh[tid] = fmaxf(sh[tid], sh[tid + st]);
        __syncthreads();
    }
    float m = sh[0];
    __syncthreads();
    float e = (tid < len) ? expf(v - m) : 0.f;
    sh[tid] = e;
    __syncthreads();
    for (int st = 64; st > 0; st >>= 1) {
        if (tid < st) sh[tid] += sh[tid + st];
        __syncthreads();
    }
    float z = sh[0];
    if (tid < len) g_attn[off + tid] = e / z;
}

// ---------------------------------------------------------------------------
// K4b: out[n,f] = attn[n] * g_rowsum[n][f]
// ---------------------------------------------------------------------------
__global__ __launch_bounds__(256) void k4_out(float* __restrict__ out) {
    int idx = blockIdx.x * 256 + threadIdx.x;
    int n = idx >> 6;
    float a = g_attn[n];
    float4 v = ((const float4*)g_rowsum)[idx];
    v.x *= a; v.y *= a; v.z *= a; v.w *= a;
    ((float4*)out)[idx] = v;
}

// ---------------------------------------------------------------------------
extern "C" void kernel_launch(void* const* d_in, const int* in_sizes, int n_in,
                              void* d_out, int out_size) {
    const float* x      = (const float*)d_in[0];
    const float* hidden = (const float*)d_in[1];
    const float* W1     = (const float*)d_in[2];
    const float* b1     = (const float*)d_in[3];
    const float* W2     = (const float*)d_in[4];
    const float* b2     = (const float*)d_in[5];
    const int* pl       = (const int*)d_in[6];

    float* out = (float*)d_out;

    static bool s_init = false;
    static cudaStream_t s_side;
    static cudaEvent_t s_eFork, s_eJoin;
    if (!s_init) {
        cudaFuncSetAttribute(k2_scores, cudaFuncAttributeMaxDynamicSharedMemorySize, K2_SMEM);
        cudaFuncSetAttribute(k1m_x2, cudaFuncAttributeMaxDynamicSharedMemorySize, K1M_SMEM);
        cudaStreamCreateWithFlags(&s_side, cudaStreamNonBlocking);
        cudaEventCreateWithFlags(&s_eFork, cudaEventDisableTiming);
        cudaEventCreateWithFlags(&s_eJoin, cudaEventDisableTiming);
        s_init = true;
    }

    // slot layout: k0(1), k4a(2), k1m(3), k2(4 = ncu capture slot)
    k0_prep<<<256, 256>>>(W1, W2);

    cudaEventRecord(s_eFork, 0);
    cudaStreamWaitEvent(s_side, s_eFork, 0);
    k4a_rowsum<<<148, 128, 0, s_side>>>(x);   // persistent, co-resident

    k1m_x2<<<dim3(64, 2), 256, K1M_SMEM>>>(hidden, b2);
    k2_scores<<<MTOT / 128, 256, K2_SMEM>>>(x, b1);

    cudaEventRecord(s_eJoin, s_side);
    cudaStreamWaitEvent(0, s_eJoin, 0);

    k3_softmax<<<SS, 128>>>(pl);
    k4_out<<<2048, 256>>>(out);
}

// round 14
// speedup vs baseline: 1.5997x; 1.5997x over previous
#include <cuda_runtime.h>
#include <cuda_fp16.h>
#include <cstdint>

#define NN 8192
#define PP 49
#define FF 256
#define EE 256
#define HH 256
#define SS 128
#define MTOT (NN * PP)  // 401408

// Scratch (no allocations allowed)
__device__ float  g_x2[NN * EE];      // 8 MB
__device__ __half g_w1h[EE * FF];     // 128 KB fp16 W1
__device__ __half g_w2h[EE * HH];     // 128 KB fp16 W2
__device__ float  g_scores[NN];
__device__ float  g_attn[NN];

// ---------------------------------------------------------------------------
// helpers
// ---------------------------------------------------------------------------
__device__ __forceinline__ uint32_t smem_u32(const void* p) {
    uint32_t a;
    asm("{ .reg .u64 t; cvta.to.shared.u64 t, %1; cvt.u32.u64 %0, t; }" : "=r"(a) : "l"(p));
    return a;
}
__device__ __forceinline__ float ftanh(float x) {   // err ~1e-6
    float e = __expf(2.f * x);
    return 1.f - __fdividef(2.f, e + 1.f);
}
__device__ __forceinline__ float tanha(float x) {   // MUFU tanh
    float y;
    asm("tanh.approx.f32 %0, %1;" : "=f"(y) : "f"(x));
    return y;
}

#define LDSM4(r, addr) \
    asm volatile("ldmatrix.sync.aligned.m8n8.x4.shared.b16 {%0,%1,%2,%3}, [%4];" \
        : "=r"((r)[0]), "=r"((r)[1]), "=r"((r)[2]), "=r"((r)[3]) : "r"(addr))

#define MMA16816(c, a, b0v, b1v) \
    asm volatile("mma.sync.aligned.m16n8k16.row.col.f32.f16.f16.f32 " \
        "{%0,%1,%2,%3},{%4,%5,%6,%7},{%8,%9},{%0,%1,%2,%3};" \
        : "+f"((c)[0]), "+f"((c)[1]), "+f"((c)[2]), "+f"((c)[3]) \
        : "r"((a)[0]), "r"((a)[1]), "r"((a)[2]), "r"((a)[3]), "r"(b0v), "r"(b1v))

__device__ __forceinline__ uint32_t pack_h2(float a, float b) {
    __half2 h = __floats2half2_rn(a, b);
    return *(uint32_t*)&h;
}

__global__ void kdummy() {}

// ---------------------------------------------------------------------------
// K0: convert W1,W2 -> fp16; zero g_scores.
// ---------------------------------------------------------------------------
__global__ __launch_bounds__(256) void k0_prep(const float* __restrict__ W1,
                                               const float* __restrict__ W2) {
    int i = blockIdx.x * 256 + threadIdx.x;   // 0..65535
    g_w1h[i] = __float2half_rn(W1[i]);
    g_w2h[i] = __float2half_rn(W2[i]);
    if (i < NN) g_scores[i] = 0.f;
}

// ---------------------------------------------------------------------------
// K1M: x2 = tanh(H . W2^T + b2) via fp16 mma (f32 acc).  Verified in R13
// (rel_err 3.03e-4).  CTA = 128 rows x 128 e-half, grid (64,2), 8 warps.
// ---------------------------------------------------------------------------
#define M_OFF_B2  0
#define M_OFF_BW  2688
#define M_OFF_A   70272
#define M_A_BUF   10240
#define K1M_SMEM  90752

__global__ __launch_bounds__(256, 2) void k1m_x2(const float* __restrict__ Hm,
                                                 const float* __restrict__ b2) {
    extern __shared__ __align__(16) char smem[];
    float* b2s = (float*)(smem + M_OFF_B2);

    const int tid = threadIdx.x;
    const int w = tid >> 5, lane = tid & 31;
    const int tig = lane & 3, g = lane >> 2;
    const int wm = w >> 2, wn = w & 3;
    const int row0 = blockIdx.x * 128;
    const int e0 = blockIdx.y * 128;

    const float* Xp = Hm + (size_t)(row0 + (tid >> 1)) * HH + (tid & 1) * 16;
    float4 pr0 = *(const float4*)(Xp + 0);
    float4 pr1 = *(const float4*)(Xp + 4);
    float4 pr2 = *(const float4*)(Xp + 8);
    float4 pr3 = *(const float4*)(Xp + 12);

    {
        const uint4* Wp = (const uint4*)(g_w2h + (size_t)e0 * HH);
        for (int i = tid; i < 4096; i += 256) {
            int r = i >> 5, s2 = i & 31;
            *(uint4*)(smem + M_OFF_BW + r * 528 + s2 * 16) = Wp[i];
        }
    }
    if (tid < 128) b2s[tid] = b2[e0 + tid];

    float acc[4][4][4];
#pragma unroll
    for (int mt = 0; mt < 4; mt++)
#pragma unroll
        for (int nt = 0; nt < 4; nt++)
#pragma unroll
            for (int i = 0; i < 4; i++) acc[mt][nt][i] = 0.f;

    const uint32_t sb = smem_u32(smem);
    const int arow = lane & 15, asel = lane >> 4;
    const uint32_t aAddr0 = sb + M_OFF_A + (uint32_t)(wm * 64 + arow) * 80 + asel * 16;
    const int brow = (lane & 7) + ((lane >> 4) << 3), bsel = (lane >> 3) & 1;
    const uint32_t bAddr0 = sb + M_OFF_BW + (uint32_t)(wn * 32 + brow) * 528 + bsel * 16;
    char* stsP = smem + M_OFF_A + (tid >> 1) * 80 + (tid & 1) * 32;

    for (int kc = 0; kc < 8; kc++) {
        const uint32_t bo = (kc & 1) * M_A_BUF;
        {
            uint4 q0, q1;
            q0.x = pack_h2(pr0.x, pr0.y); q0.y = pack_h2(pr0.z, pr0.w);
            q0.z = pack_h2(pr1.x, pr1.y); q0.w = pack_h2(pr1.z, pr1.w);
            q1.x = pack_h2(pr2.x, pr2.y); q1.y = pack_h2(pr2.z, pr2.w);
            q1.z = pack_h2(pr3.x, pr3.y); q1.w = pack_h2(pr3.z, pr3.w);
            *(uint4*)(stsP + bo) = q0;
            *(uint4*)(stsP + bo + 16) = q1;
        }
        __syncthreads();
        if (kc < 7) {
            const float* Xn = Xp + (kc + 1) * 32;
            pr0 = *(const float4*)(Xn + 0);
            pr1 = *(const float4*)(Xn + 4);
            pr2 = *(const float4*)(Xn + 8);
            pr3 = *(const float4*)(Xn + 12);
        }
#pragma unroll
        for (int ks = 0; ks < 2; ks++) {
            uint32_t Ar[4][4], Br[2][4];
#pragma unroll
            for (int mt = 0; mt < 4; mt++)
                LDSM4(Ar[mt], aAddr0 + bo + mt * (16 * 80) + ks * 32);
#pragma unroll
            for (int np = 0; np < 2; np++)
                LDSM4(Br[np], bAddr0 + np * (16 * 528) + kc * 64 + ks * 32);
#pragma unroll
            for (int mt = 0; mt < 4; mt++)
#pragma unroll
                for (int nt = 0; nt < 4; nt++)
                    MMA16816(acc[mt][nt], Ar[mt], Br[nt >> 1][(nt & 1) * 2],
                             Br[nt >> 1][(nt & 1) * 2 + 1]);
        }
    }

    float b0r[4], b1r[4];
#pragma unroll
    for (int nt = 0; nt < 4; nt++) {
        b0r[nt] = b2s[wn * 32 + nt * 8 + tig * 2];
        b1r[nt] = b2s[wn * 32 + nt * 8 + tig * 2 + 1];
    }
#pragma unroll
    for (int mt = 0; mt < 4; mt++) {
        int rA = row0 + wm * 64 + mt * 16 + g;
        int rB = rA + 8;
#pragma unroll
        for (int nt = 0; nt < 4; nt++) {
            int e = e0 + wn * 32 + nt * 8 + tig * 2;
            float2 vA = make_float2(ftanh(acc[mt][nt][0] + b0r[nt]),
                                    ftanh(acc[mt][nt][1] + b1r[nt]));
            float2 vB = make_float2(ftanh(acc[mt][nt][2] + b0r[nt]),
                                    ftanh(acc[mt][nt][3] + b1r[nt]));
            *(float2*)&g_x2[(size_t)rA * EE + e] = vA;
            *(float2*)&g_x2[(size_t)rB * EE + e] = vB;
        }
    }
}

// ---------------------------------------------------------------------------
// K2: R4 verbatim — best measured config (446us solo in R11).
// ---------------------------------------------------------------------------
#define OFF_B1  0
#define OFF_X2  1024
#define OFF_BW  5248
#define OFF_A   140416
#define A_BUF   10240
#define K2_SMEM 160896

__global__ __launch_bounds__(256, 1) void k2_scores(const float* __restrict__ X,
                                                    const float* __restrict__ b1) {
    extern __shared__ __align__(16) char smem[];
    float* b1s = (float*)(smem + OFF_B1);
    float* x2s = (float*)(smem + OFF_X2);

    const int tid = threadIdx.x;
    const int w = tid >> 5, lane = tid & 31;
    const int tig = lane & 3, g = lane >> 2;
    const int wm = w >> 2, wn = w & 3;
    const int row0 = blockIdx.x * 128;
    const int n0 = row0 / PP;

    const float* Xp = X + (size_t)(row0 + (tid >> 1)) * FF + (tid & 1) * 16;
    float4 pr0 = *(const float4*)(Xp + 0);
    float4 pr1 = *(const float4*)(Xp + 4);
    float4 pr2 = *(const float4*)(Xp + 8);
    float4 pr3 = *(const float4*)(Xp + 12);

    {
        const uint4* Wp = (const uint4*)g_w1h;
        for (int i = tid; i < 8192; i += 256) {
            int r = i >> 5, s2 = i & 31;
            *(uint4*)(smem + OFF_BW + r * 528 + s2 * 16) = Wp[i];
        }
    }
    for (int i = tid; i < 4 * EE; i += 256) {
        int s = i >> 8, e = i & 255;
        int n = n0 + s;
        x2s[s * 260 + e] = (n < NN) ? g_x2[(size_t)n * EE + e] : 0.f;
    }
    if (tid < EE) b1s[tid] = b1[tid];

    float acc[4][8][4];
#pragma unroll
    for (int mt = 0; mt < 4; mt++)
#pragma unroll
        for (int nt = 0; nt < 8; nt++)
#pragma unroll
            for (int i = 0; i < 4; i++) acc[mt][nt][i] = 0.f;

    const uint32_t sb = smem_u32(smem);
    const int arow = lane & 15, asel = lane >> 4;
    const uint32_t aAddr0 = sb + OFF_A + (uint32_t)(wm * 64 + arow) * 80 + asel * 16;
    const int brow = (lane & 7) + ((lane >> 4) << 3), bsel = (lane >> 3) & 1;
    const uint32_t bAddr0 = sb + OFF_BW + (uint32_t)(wn * 64 + brow) * 528 + bsel * 16;
    char* stsP = smem + OFF_A + (tid >> 1) * 80 + (tid & 1) * 32;

    for (int kc = 0; kc < 8; kc++) {
        const uint32_t bo = (kc & 1) * A_BUF;
        {
            uint4 q0, q1;
            q0.x = pack_h2(pr0.x, pr0.y); q0.y = pack_h2(pr0.z, pr0.w);
            q0.z = pack_h2(pr1.x, pr1.y); q0.w = pack_h2(pr1.z, pr1.w);
            q1.x = pack_h2(pr2.x, pr2.y); q1.y = pack_h2(pr2.z, pr2.w);
            q1.z = pack_h2(pr3.x, pr3.y); q1.w = pack_h2(pr3.z, pr3.w);
            *(uint4*)(stsP + bo) = q0;
            *(uint4*)(stsP + bo + 16) = q1;
        }
        __syncthreads();
        if (kc < 7) {
            const float* Xn = Xp + (kc + 1) * 32;
            pr0 = *(const float4*)(Xn + 0);
            pr1 = *(const float4*)(Xn + 4);
            pr2 = *(const float4*)(Xn + 8);
            pr3 = *(const float4*)(Xn + 12);
        }
#pragma unroll
        for (int ks = 0; ks < 2; ks++) {
            uint32_t Ar[4][4], Br[4][4];
#pragma unroll
            for (int mt = 0; mt < 4; mt++)
                LDSM4(Ar[mt], aAddr0 + bo + mt * (16 * 80) + ks * 32);
#pragma unroll
            for (int np = 0; np < 4; np++)
                LDSM4(Br[np], bAddr0 + np * (16 * 528) + kc * 64 + ks * 32);
#pragma unroll
            for (int mt = 0; mt < 4; mt++)
#pragma unroll
                for (int nt = 0; nt < 8; nt++)
                    MMA16816(acc[mt][nt], Ar[mt], Br[nt >> 1][(nt & 1) * 2],
                             Br[nt >> 1][(nt & 1) * 2 + 1]);
        }
    }

    const float inv = 1.f / (float)PP;
    float b0r[8], b1r[8];
#pragma unroll
    for (int nt = 0; nt < 8; nt++) {
        b0r[nt] = b1s[wn * 64 + nt * 8 + tig * 2];
        b1r[nt] = b1s[wn * 64 + nt * 8 + tig * 2 + 1];
    }
#pragma unroll
    for (int mt = 0; mt < 4; mt++) {
        int rA = wm * 64 + mt * 16 + g;
        int rB = rA + 8;
        int nA = (row0 + rA) / PP;
        int nB = (row0 + rB) / PP;
        const float* xA = x2s + (nA - n0) * 260 + wn * 64;
        const float* xB = x2s + (nB - n0) * 260 + wn * 64;
        float sA = 0.f, sB = 0.f;
#pragma unroll
        for (int nt = 0; nt < 8; nt++) {
            int c0 = nt * 8 + tig * 2, c1 = c0 + 1;
            sA += tanha(acc[mt][nt][0] + b0r[nt]) * xA[c0]
                + tanha(acc[mt][nt][1] + b1r[nt]) * xA[c1];
            sB += tanha(acc[mt][nt][2] + b0r[nt]) * xB[c0]
                + tanha(acc[mt][nt][3] + b1r[nt]) * xB[c1];
        }
        sA += __shfl_xor_sync(0xffffffffu, sA, 1);
        sA += __shfl_xor_sync(0xffffffffu, sA, 2);
        sB += __shfl_xor_sync(0xffffffffu, sB, 1);
        sB += __shfl_xor_sync(0xffffffffu, sB, 2);
        if (tig == 0) {
            atomicAdd(&g_scores[nA], sA * inv);
            atomicAdd(&g_scores[nB], sB * inv);
        }
    }
}

// ---------------------------------------------------------------------------
// K3: per-segment softmax over scalar scores (patch_lens int32 or int64).
// ---------------------------------------------------------------------------
__device__ __forceinline__ int seg_len(const int* p32, int is64, int i) {
    return is64 ? p32[2 * i] : p32[i];
}

__global__ __launch_bounds__(128) void k3_softmax(const int* __restrict__ lens32) {
    __shared__ float sh[128];
    __shared__ int s_off, s_len;
    int s = blockIdx.x, tid = threadIdx.x;
    if (tid == 0) {
        int is64 = (lens32[1] == 0) ? 1 : 0;
        int o = 0;
        for (int i = 0; i < s; i++) o += seg_len(lens32, is64, i);
        s_off = o;
        s_len = seg_len(lens32, is64, s);
    }
    __syncthreads();
    int off = s_off, len = s_len;
    float v = (tid < len) ? g_scores[off + tid] : -1e30f;
    sh[tid] = v;
    __syncthreads();
    for (int st = 64; st > 0; st >>= 1) {
        if (tid < st) sh[tid] = fmaxf(sh[tid], sh[tid + st]);
        __syncthreads();
    }
    float m = sh[0];
    __syncthreads();
    float e = (tid < len) ? expf(v - m) : 0.f;
    sh[tid] = e;
    __syncthreads();
    for (int st = 64; st > 0; st >>= 1) {
        if (tid < st) sh[tid] += sh[tid + st];
        __syncthreads();
    }
    float z = sh[0];
    if (tid < len) g_attn[off + tid] = e / z;
}

// ---------------------------------------------------------------------------
// K4: out[n,f] = attn[n] * sum_p x[n,p,f]   (R4-proven, ~82% DRAM peak)
// ---------------------------------------------------------------------------
__global__ __launch_bounds__(256) void k4_out(const float* __restrict__ X,
                                              float* __restrict__ out) {
    int n = blockIdx.x, f = threadIdx.x;
    const float* xp = X + (size_t)n * PP * FF + f;
    float acc = 0.f;
#pragma unroll
    for (int p = 0; p < PP; p++) acc += xp[(size_t)p * FF];
    out[(size_t)n * FF + f] = acc * g_attn[n];
}

// ---------------------------------------------------------------------------
extern "C" void kernel_launch(void* const* d_in, const int* in_sizes, int n_in,
                              void* d_out, int out_size) {
    const float* x      = (const float*)d_in[0];
    const float* hidden = (const float*)d_in[1];
    const float* W1     = (const float*)d_in[2];
    const float* b1     = (const float*)d_in[3];
    const float* W2     = (const float*)d_in[4];
    const float* b2     = (const float*)d_in[5];
    const int* pl       = (const int*)d_in[6];

    float* out = (float*)d_out;

    static bool s_init = false;
    if (!s_init) {
        cudaFuncSetAttribute(k2_scores, cudaFuncAttributeMaxDynamicSharedMemorySize, K2_SMEM);
        cudaFuncSetAttribute(k1m_x2, cudaFuncAttributeMaxDynamicSharedMemorySize, K1M_SMEM);
        s_init = true;
    }

    // fully serial, default stream; k2 at launch slot 4 (ncu capture)
    k0_prep<<<256, 256>>>(W1, W2);
    kdummy<<<1, 32>>>();
    k1m_x2<<<dim3(64, 2), 256, K1M_SMEM>>>(hidden, b2);
    k2_scores<<<MTOT / 128, 256, K2_SMEM>>>(x, b1);
    k3_softmax<<<SS, 128>>>(pl);
    k4_out<<<NN, 256>>>(x, out);
}

// round 15
// speedup vs baseline: 1.6007x; 1.0007x over previous
#include <cuda_runtime.h>
#include <cuda_fp16.h>
#include <cstdint>

#define NN 8192
#define PP 49
#define FF 256
#define EE 256
#define HH 256
#define SS 128
#define MTOT (NN * PP)  // 401408

// Scratch (no allocations allowed)
__device__ float  g_x2[NN * EE];      // 8 MB
__device__ __half g_w1h[EE * FF];     // 128 KB fp16 W1
__device__ __half g_w2h[EE * HH];     // 128 KB fp16 W2
__device__ float  g_scores[NN];
__device__ float  g_attn[NN];

// ---------------------------------------------------------------------------
// helpers
// ---------------------------------------------------------------------------
__device__ __forceinline__ uint32_t smem_u32(const void* p) {
    uint32_t a;
    asm("{ .reg .u64 t; cvta.to.shared.u64 t, %1; cvt.u32.u64 %0, t; }" : "=r"(a) : "l"(p));
    return a;
}
__device__ __forceinline__ float ftanh(float x) {   // err ~1e-6
    float e = __expf(2.f * x);
    return 1.f - __fdividef(2.f, e + 1.f);
}
__device__ __forceinline__ float tanha(float x) {   // MUFU tanh
    float y;
    asm("tanh.approx.f32 %0, %1;" : "=f"(y) : "f"(x));
    return y;
}

#define LDSM4(r, addr) \
    asm volatile("ldmatrix.sync.aligned.m8n8.x4.shared.b16 {%0,%1,%2,%3}, [%4];" \
        : "=r"((r)[0]), "=r"((r)[1]), "=r"((r)[2]), "=r"((r)[3]) : "r"(addr))

// f32-acc (k1m)
#define MMA16816(c, a, b0v, b1v) \
    asm volatile("mma.sync.aligned.m16n8k16.row.col.f32.f16.f16.f32 " \
        "{%0,%1,%2,%3},{%4,%5,%6,%7},{%8,%9},{%0,%1,%2,%3};" \
        : "+f"((c)[0]), "+f"((c)[1]), "+f"((c)[2]), "+f"((c)[3]) \
        : "r"((a)[0]), "r"((a)[1]), "r"((a)[2]), "r"((a)[3]), "r"(b0v), "r"(b1v))

// f16-acc (k2): C/D are 2x b32 (half2) regs — tests rt(F16acc) = rt(F32acc)/2
#define MMA16816F16(c, a, b0v, b1v) \
    asm volatile("mma.sync.aligned.m16n8k16.row.col.f16.f16.f16.f16 " \
        "{%0,%1},{%2,%3,%4,%5},{%6,%7},{%0,%1};" \
        : "+r"((c)[0]), "+r"((c)[1]) \
        : "r"((a)[0]), "r"((a)[1]), "r"((a)[2]), "r"((a)[3]), "r"(b0v), "r"(b1v))

__device__ __forceinline__ uint32_t pack_h2(float a, float b) {
    __half2 h = __floats2half2_rn(a, b);
    return *(uint32_t*)&h;
}

__global__ void kdummy() {}

// ---------------------------------------------------------------------------
// K0: convert W1,W2 -> fp16; zero g_scores.
// ---------------------------------------------------------------------------
__global__ __launch_bounds__(256) void k0_prep(const float* __restrict__ W1,
                                               const float* __restrict__ W2) {
    int i = blockIdx.x * 256 + threadIdx.x;   // 0..65535
    g_w1h[i] = __float2half_rn(W1[i]);
    g_w2h[i] = __float2half_rn(W2[i]);
    if (i < NN) g_scores[i] = 0.f;
}

// ---------------------------------------------------------------------------
// K1M: x2 = tanh(H . W2^T + b2) via fp16 mma (f32 acc).  R13/R14-verified.
// ---------------------------------------------------------------------------
#define M_OFF_B2  0
#define M_OFF_BW  2688
#define M_OFF_A   70272
#define M_A_BUF   10240
#define K1M_SMEM  90752

__global__ __launch_bounds__(256, 2) void k1m_x2(const float* __restrict__ Hm,
                                                 const float* __restrict__ b2) {
    extern __shared__ __align__(16) char smem[];
    float* b2s = (float*)(smem + M_OFF_B2);

    const int tid = threadIdx.x;
    const int w = tid >> 5, lane = tid & 31;
    const int tig = lane & 3, g = lane >> 2;
    const int wm = w >> 2, wn = w & 3;
    const int row0 = blockIdx.x * 128;
    const int e0 = blockIdx.y * 128;

    const float* Xp = Hm + (size_t)(row0 + (tid >> 1)) * HH + (tid & 1) * 16;
    float4 pr0 = *(const float4*)(Xp + 0);
    float4 pr1 = *(const float4*)(Xp + 4);
    float4 pr2 = *(const float4*)(Xp + 8);
    float4 pr3 = *(const float4*)(Xp + 12);

    {
        const uint4* Wp = (const uint4*)(g_w2h + (size_t)e0 * HH);
        for (int i = tid; i < 4096; i += 256) {
            int r = i >> 5, s2 = i & 31;
            *(uint4*)(smem + M_OFF_BW + r * 528 + s2 * 16) = Wp[i];
        }
    }
    if (tid < 128) b2s[tid] = b2[e0 + tid];

    float acc[4][4][4];
#pragma unroll
    for (int mt = 0; mt < 4; mt++)
#pragma unroll
        for (int nt = 0; nt < 4; nt++)
#pragma unroll
            for (int i = 0; i < 4; i++) acc[mt][nt][i] = 0.f;

    const uint32_t sb = smem_u32(smem);
    const int arow = lane & 15, asel = lane >> 4;
    const uint32_t aAddr0 = sb + M_OFF_A + (uint32_t)(wm * 64 + arow) * 80 + asel * 16;
    const int brow = (lane & 7) + ((lane >> 4) << 3), bsel = (lane >> 3) & 1;
    const uint32_t bAddr0 = sb + M_OFF_BW + (uint32_t)(wn * 32 + brow) * 528 + bsel * 16;
    char* stsP = smem + M_OFF_A + (tid >> 1) * 80 + (tid & 1) * 32;

    for (int kc = 0; kc < 8; kc++) {
        const uint32_t bo = (kc & 1) * M_A_BUF;
        {
            uint4 q0, q1;
            q0.x = pack_h2(pr0.x, pr0.y); q0.y = pack_h2(pr0.z, pr0.w);
            q0.z = pack_h2(pr1.x, pr1.y); q0.w = pack_h2(pr1.z, pr1.w);
            q1.x = pack_h2(pr2.x, pr2.y); q1.y = pack_h2(pr2.z, pr2.w);
            q1.z = pack_h2(pr3.x, pr3.y); q1.w = pack_h2(pr3.z, pr3.w);
            *(uint4*)(stsP + bo) = q0;
            *(uint4*)(stsP + bo + 16) = q1;
        }
        __syncthreads();
        if (kc < 7) {
            const float* Xn = Xp + (kc + 1) * 32;
            pr0 = *(const float4*)(Xn + 0);
            pr1 = *(const float4*)(Xn + 4);
            pr2 = *(const float4*)(Xn + 8);
            pr3 = *(const float4*)(Xn + 12);
        }
#pragma unroll
        for (int ks = 0; ks < 2; ks++) {
            uint32_t Ar[4][4], Br[2][4];
#pragma unroll
            for (int mt = 0; mt < 4; mt++)
                LDSM4(Ar[mt], aAddr0 + bo + mt * (16 * 80) + ks * 32);
#pragma unroll
            for (int np = 0; np < 2; np++)
                LDSM4(Br[np], bAddr0 + np * (16 * 528) + kc * 64 + ks * 32);
#pragma unroll
            for (int mt = 0; mt < 4; mt++)
#pragma unroll
                for (int nt = 0; nt < 4; nt++)
                    MMA16816(acc[mt][nt], Ar[mt], Br[nt >> 1][(nt & 1) * 2],
                             Br[nt >> 1][(nt & 1) * 2 + 1]);
        }
    }

    float b0r[4], b1r[4];
#pragma unroll
    for (int nt = 0; nt < 4; nt++) {
        b0r[nt] = b2s[wn * 32 + nt * 8 + tig * 2];
        b1r[nt] = b2s[wn * 32 + nt * 8 + tig * 2 + 1];
    }
#pragma unroll
    for (int mt = 0; mt < 4; mt++) {
        int rA = row0 + wm * 64 + mt * 16 + g;
        int rB = rA + 8;
#pragma unroll
        for (int nt = 0; nt < 4; nt++) {
            int e = e0 + wn * 32 + nt * 8 + tig * 2;
            float2 vA = make_float2(ftanh(acc[mt][nt][0] + b0r[nt]),
                                    ftanh(acc[mt][nt][1] + b1r[nt]));
            float2 vB = make_float2(ftanh(acc[mt][nt][2] + b0r[nt]),
                                    ftanh(acc[mt][nt][3] + b1r[nt]));
            *(float2*)&g_x2[(size_t)rA * EE + e] = vA;
            *(float2*)&g_x2[(size_t)rB * EE + e] = vB;
        }
    }
}

// ---------------------------------------------------------------------------
// K2: R14 structure verbatim, accumulators switched f32 -> f16.
// Tests H: rt_SMSP(HMMA f16-acc) = rt(f32-acc)/2 -> k2 444 -> ~300us.
// ---------------------------------------------------------------------------
#define OFF_B1  0
#define OFF_X2  1024
#define OFF_BW  5248
#define OFF_A   140416
#define A_BUF   10240
#define K2_SMEM 160896

__global__ __launch_bounds__(256, 1) void k2_scores(const float* __restrict__ X,
                                                    const float* __restrict__ b1) {
    extern __shared__ __align__(16) char smem[];
    float* b1s = (float*)(smem + OFF_B1);
    float* x2s = (float*)(smem + OFF_X2);

    const int tid = threadIdx.x;
    const int w = tid >> 5, lane = tid & 31;
    const int tig = lane & 3, g = lane >> 2;
    const int wm = w >> 2, wn = w & 3;
    const int row0 = blockIdx.x * 128;
    const int n0 = row0 / PP;

    const float* Xp = X + (size_t)(row0 + (tid >> 1)) * FF + (tid & 1) * 16;
    float4 pr0 = *(const float4*)(Xp + 0);
    float4 pr1 = *(const float4*)(Xp + 4);
    float4 pr2 = *(const float4*)(Xp + 8);
    float4 pr3 = *(const float4*)(Xp + 12);

    {
        const uint4* Wp = (const uint4*)g_w1h;
        for (int i = tid; i < 8192; i += 256) {
            int r = i >> 5, s2 = i & 31;
            *(uint4*)(smem + OFF_BW + r * 528 + s2 * 16) = Wp[i];
        }
    }
    for (int i = tid; i < 4 * EE; i += 256) {
        int s = i >> 8, e = i & 255;
        int n = n0 + s;
        x2s[s * 260 + e] = (n < NN) ? g_x2[(size_t)n * EE + e] : 0.f;
    }
    if (tid < EE) b1s[tid] = b1[tid];

    uint32_t acc16[4][8][2];
#pragma unroll
    for (int mt = 0; mt < 4; mt++)
#pragma unroll
        for (int nt = 0; nt < 8; nt++) {
            acc16[mt][nt][0] = 0u;
            acc16[mt][nt][1] = 0u;
        }

    const uint32_t sb = smem_u32(smem);
    const int arow = lane & 15, asel = lane >> 4;
    const uint32_t aAddr0 = sb + OFF_A + (uint32_t)(wm * 64 + arow) * 80 + asel * 16;
    const int brow = (lane & 7) + ((lane >> 4) << 3), bsel = (lane >> 3) & 1;
    const uint32_t bAddr0 = sb + OFF_BW + (uint32_t)(wn * 64 + brow) * 528 + bsel * 16;
    char* stsP = smem + OFF_A + (tid >> 1) * 80 + (tid & 1) * 32;

    for (int kc = 0; kc < 8; kc++) {
        const uint32_t bo = (kc & 1) * A_BUF;
        {
            uint4 q0, q1;
            q0.x = pack_h2(pr0.x, pr0.y); q0.y = pack_h2(pr0.z, pr0.w);
            q0.z = pack_h2(pr1.x, pr1.y); q0.w = pack_h2(pr1.z, pr1.w);
            q1.x = pack_h2(pr2.x, pr2.y); q1.y = pack_h2(pr2.z, pr2.w);
            q1.z = pack_h2(pr3.x, pr3.y); q1.w = pack_h2(pr3.z, pr3.w);
            *(uint4*)(stsP + bo) = q0;
            *(uint4*)(stsP + bo + 16) = q1;
        }
        __syncthreads();
        if (kc < 7) {
            const float* Xn = Xp + (kc + 1) * 32;
            pr0 = *(const float4*)(Xn + 0);
            pr1 = *(const float4*)(Xn + 4);
            pr2 = *(const float4*)(Xn + 8);
            pr3 = *(const float4*)(Xn + 12);
        }
#pragma unroll
        for (int ks = 0; ks < 2; ks++) {
            uint32_t Ar[4][4], Br[4][4];
#pragma unroll
            for (int mt = 0; mt < 4; mt++)
                LDSM4(Ar[mt], aAddr0 + bo + mt * (16 * 80) + ks * 32);
#pragma unroll
            for (int np = 0; np < 4; np++)
                LDSM4(Br[np], bAddr0 + np * (16 * 528) + kc * 64 + ks * 32);
#pragma unroll
            for (int mt = 0; mt < 4; mt++)
#pragma unroll
                for (int nt = 0; nt < 8; nt++)
                    MMA16816F16(acc16[mt][nt], Ar[mt], Br[nt >> 1][(nt & 1) * 2],
                                Br[nt >> 1][(nt & 1) * 2 + 1]);
        }
    }

    const float inv = 1.f / (float)PP;
    float b0r[8], b1r[8];
#pragma unroll
    for (int nt = 0; nt < 8; nt++) {
        b0r[nt] = b1s[wn * 64 + nt * 8 + tig * 2];
        b1r[nt] = b1s[wn * 64 + nt * 8 + tig * 2 + 1];
    }
#pragma unroll
    for (int mt = 0; mt < 4; mt++) {
        int rA = wm * 64 + mt * 16 + g;
        int rB = rA + 8;
        int nA = (row0 + rA) / PP;
        int nB = (row0 + rB) / PP;
        const float* xA = x2s + (nA - n0) * 260 + wn * 64;
        const float* xB = x2s + (nB - n0) * 260 + wn * 64;
        float sA = 0.f, sB = 0.f;
#pragma unroll
        for (int nt = 0; nt < 8; nt++) {
            int c0 = nt * 8 + tig * 2, c1 = c0 + 1;
            float2 lo = __half22float2(*(__half2*)&acc16[mt][nt][0]);
            float2 hi = __half22float2(*(__half2*)&acc16[mt][nt][1]);
            sA += tanha(lo.x + b0r[nt]) * xA[c0] + tanha(lo.y + b1r[nt]) * xA[c1];
            sB += tanha(hi.x + b0r[nt]) * xB[c0] + tanha(hi.y + b1r[nt]) * xB[c1];
        }
        sA += __shfl_xor_sync(0xffffffffu, sA, 1);
        sA += __shfl_xor_sync(0xffffffffu, sA, 2);
        sB += __shfl_xor_sync(0xffffffffu, sB, 1);
        sB += __shfl_xor_sync(0xffffffffu, sB, 2);
        if (tig == 0) {
            atomicAdd(&g_scores[nA], sA * inv);
            atomicAdd(&g_scores[nB], sB * inv);
        }
    }
}

// ---------------------------------------------------------------------------
// K3: per-segment softmax over scalar scores (patch_lens int32 or int64).
// ---------------------------------------------------------------------------
__device__ __forceinline__ int seg_len(const int* p32, int is64, int i) {
    return is64 ? p32[2 * i] : p32[i];
}

__global__ __launch_bounds__(128) void k3_softmax(const int* __restrict__ lens32) {
    __shared__ float sh[128];
    __shared__ int s_off, s_len;
    int s = blockIdx.x, tid = threadIdx.x;
    if (tid == 0) {
        int is64 = (lens32[1] == 0) ? 1 : 0;
        int o = 0;
        for (int i = 0; i < s; i++) o += seg_len(lens32, is64, i);
        s_off = o;
        s_len = seg_len(lens32, is64, s);
    }
    __syncthreads();
    int off = s_off, len = s_len;
    float v = (tid < len) ? g_scores[off + tid] : -1e30f;
    sh[tid] = v;
    __syncthreads();
    for (int st = 64; st > 0; st >>= 1) {
        if (tid < st) sh[tid] = fmaxf(sh[tid], sh[tid + st]);
        __syncthreads();
    }
    float m = sh[0];
    __syncthreads();
    float e = (tid < len) ? expf(v - m) : 0.f;
    sh[tid] = e;
    __syncthreads();
    for (int st = 64; st > 0; st >>= 1) {
        if (tid < st) sh[tid] += sh[tid + st];
        __syncthreads();
    }
    float z = sh[0];
    if (tid < len) g_attn[off + tid] = e / z;
}

// ---------------------------------------------------------------------------
// K4: out[n,f] = attn[n] * sum_p x[n,p,f]   (R4-proven, ~82% DRAM peak)
// ---------------------------------------------------------------------------
__global__ __launch_bounds__(256) void k4_out(const float* __restrict__ X,
                                              float* __restrict__ out) {
    int n = blockIdx.x, f = threadIdx.x;
    const float* xp = X + (size_t)n * PP * FF + f;
    float acc = 0.f;
#pragma unroll
    for (int p = 0; p < PP; p++) acc += xp[(size_t)p * FF];
    out[(size_t)n * FF + f] = acc * g_attn[n];
}

// ---------------------------------------------------------------------------
extern "C" void kernel_launch(void* const* d_in, const int* in_sizes, int n_in,
                              void* d_out, int out_size) {
    const float* x      = (const float*)d_in[0];
    const float* hidden = (const float*)d_in[1];
    const float* W1     = (const float*)d_in[2];
    const float* b1     = (const float*)d_in[3];
    const float* W2     = (const float*)d_in[4];
    const float* b2     = (const float*)d_in[5];
    const int* pl       = (const int*)d_in[6];

    float* out = (float*)d_out;

    static bool s_init = false;
    if (!s_init) {
        cudaFuncSetAttribute(k2_scores, cudaFuncAttributeMaxDynamicSharedMemorySize, K2_SMEM);
        cudaFuncSetAttribute(k1m_x2, cudaFuncAttributeMaxDynamicSharedMemorySize, K1M_SMEM);
        s_init = true;
    }

    // fully serial, default stream; k2 at launch slot 4 (ncu capture)
    k0_prep<<<256, 256>>>(W1, W2);
    kdummy<<<1, 32>>>();
    k1m_x2<<<dim3(64, 2), 256, K1M_SMEM>>>(hidden, b2);
    k2_scores<<<MTOT / 128, 256, K2_SMEM>>>(x, b1);
    k3_softmax<<<SS, 128>>>(pl);
    k4_out<<<NN, 256>>>(x, out);
}

// round 16
// speedup vs baseline: 2.3282x; 1.4544x over previous
#include <cuda_runtime.h>
#include <cuda_fp16.h>
#include <cstdint>

#define NN 8192
#define PP 49
#define FF 256
#define EE 256
#define HH 256
#define SS 128
#define MTOT (NN * PP)   // 401408
#define NTILES (MTOT / 128)  // 3136

// Scratch (no allocations allowed)
__device__ float  g_x2[NN * EE];      // 8 MB
__device__ __half g_w1h[EE * FF];     // 128 KB fp16 W1
__device__ __half g_w2h[EE * HH];     // 128 KB fp16 W2
__device__ float  g_scores[NN];
__device__ float  g_attn[NN];

// ---------------------------------------------------------------------------
// helpers
// ---------------------------------------------------------------------------
__device__ __forceinline__ uint32_t smem_u32(const void* p) {
    uint32_t a;
    asm("{ .reg .u64 t; cvta.to.shared.u64 t, %1; cvt.u32.u64 %0, t; }" : "=r"(a) : "l"(p));
    return a;
}
__device__ __forceinline__ float ftanh(float x) {   // err ~1e-6
    float e = __expf(2.f * x);
    return 1.f - __fdividef(2.f, e + 1.f);
}
__device__ __forceinline__ float tanha(float x) {   // MUFU tanh
    float y;
    asm("tanh.approx.f32 %0, %1;" : "=f"(y) : "f"(x));
    return y;
}

#define LDSM4(r, addr) \
    asm volatile("ldmatrix.sync.aligned.m8n8.x4.shared.b16 {%0,%1,%2,%3}, [%4];" \
        : "=r"((r)[0]), "=r"((r)[1]), "=r"((r)[2]), "=r"((r)[3]) : "r"(addr))

#define MMA16816(c, a, b0v, b1v) \
    asm volatile("mma.sync.aligned.m16n8k16.row.col.f32.f16.f16.f32 " \
        "{%0,%1,%2,%3},{%4,%5,%6,%7},{%8,%9},{%0,%1,%2,%3};" \
        : "+f"((c)[0]), "+f"((c)[1]), "+f"((c)[2]), "+f"((c)[3]) \
        : "r"((a)[0]), "r"((a)[1]), "r"((a)[2]), "r"((a)[3]), "r"(b0v), "r"(b1v))

__device__ __forceinline__ uint32_t pack_h2(float a, float b) {
    __half2 h = __floats2half2_rn(a, b);
    return *(uint32_t*)&h;
}

__global__ void kdummy() {}

// ---------------------------------------------------------------------------
// K0: convert W1,W2 -> fp16; zero g_scores.
// ---------------------------------------------------------------------------
__global__ __launch_bounds__(256) void k0_prep(const float* __restrict__ W1,
                                               const float* __restrict__ W2) {
    int i = blockIdx.x * 256 + threadIdx.x;   // 0..65535
    g_w1h[i] = __float2half_rn(W1[i]);
    g_w2h[i] = __float2half_rn(W2[i]);
    if (i < NN) g_scores[i] = 0.f;
}

// ---------------------------------------------------------------------------
// K1M: x2 = tanh(H . W2^T + b2) via fp16 mma (f32 acc).  R13/R14-verified.
// ---------------------------------------------------------------------------
#define M_OFF_B2  0
#define M_OFF_BW  2688
#define M_OFF_A   70272
#define M_A_BUF   10240
#define K1M_SMEM  90752

__global__ __launch_bounds__(256, 2) void k1m_x2(const float* __restrict__ Hm,
                                                 const float* __restrict__ b2) {
    extern __shared__ __align__(16) char smem[];
    float* b2s = (float*)(smem + M_OFF_B2);

    const int tid = threadIdx.x;
    const int w = tid >> 5, lane = tid & 31;
    const int tig = lane & 3, g = lane >> 2;
    const int wm = w >> 2, wn = w & 3;
    const int row0 = blockIdx.x * 128;
    const int e0 = blockIdx.y * 128;

    const float* Xp = Hm + (size_t)(row0 + (tid >> 1)) * HH + (tid & 1) * 16;
    float4 pr0 = *(const float4*)(Xp + 0);
    float4 pr1 = *(const float4*)(Xp + 4);
    float4 pr2 = *(const float4*)(Xp + 8);
    float4 pr3 = *(const float4*)(Xp + 12);

    {
        const uint4* Wp = (const uint4*)(g_w2h + (size_t)e0 * HH);
        for (int i = tid; i < 4096; i += 256) {
            int r = i >> 5, s2 = i & 31;
            *(uint4*)(smem + M_OFF_BW + r * 528 + s2 * 16) = Wp[i];
        }
    }
    if (tid < 128) b2s[tid] = b2[e0 + tid];

    float acc[4][4][4];
#pragma unroll
    for (int mt = 0; mt < 4; mt++)
#pragma unroll
        for (int nt = 0; nt < 4; nt++)
#pragma unroll
            for (int i = 0; i < 4; i++) acc[mt][nt][i] = 0.f;

    const uint32_t sb = smem_u32(smem);
    const int arow = lane & 15, asel = lane >> 4;
    const uint32_t aAddr0 = sb + M_OFF_A + (uint32_t)(wm * 64 + arow) * 80 + asel * 16;
    const int brow = (lane & 7) + ((lane >> 4) << 3), bsel = (lane >> 3) & 1;
    const uint32_t bAddr0 = sb + M_OFF_BW + (uint32_t)(wn * 32 + brow) * 528 + bsel * 16;
    char* stsP = smem + M_OFF_A + (tid >> 1) * 80 + (tid & 1) * 32;

    for (int kc = 0; kc < 8; kc++) {
        const uint32_t bo = (kc & 1) * M_A_BUF;
        {
            uint4 q0, q1;
            q0.x = pack_h2(pr0.x, pr0.y); q0.y = pack_h2(pr0.z, pr0.w);
            q0.z = pack_h2(pr1.x, pr1.y); q0.w = pack_h2(pr1.z, pr1.w);
            q1.x = pack_h2(pr2.x, pr2.y); q1.y = pack_h2(pr2.z, pr2.w);
            q1.z = pack_h2(pr3.x, pr3.y); q1.w = pack_h2(pr3.z, pr3.w);
            *(uint4*)(stsP + bo) = q0;
            *(uint4*)(stsP + bo + 16) = q1;
        }
        __syncthreads();
        if (kc < 7) {
            const float* Xn = Xp + (kc + 1) * 32;
            pr0 = *(const float4*)(Xn + 0);
            pr1 = *(const float4*)(Xn + 4);
            pr2 = *(const float4*)(Xn + 8);
            pr3 = *(const float4*)(Xn + 12);
        }
#pragma unroll
        for (int ks = 0; ks < 2; ks++) {
            uint32_t Ar[4][4], Br[2][4];
#pragma unroll
            for (int mt = 0; mt < 4; mt++)
                LDSM4(Ar[mt], aAddr0 + bo + mt * (16 * 80) + ks * 32);
#pragma unroll
            for (int np = 0; np < 2; np++)
                LDSM4(Br[np], bAddr0 + np * (16 * 528) + kc * 64 + ks * 32);
#pragma unroll
            for (int mt = 0; mt < 4; mt++)
#pragma unroll
                for (int nt = 0; nt < 4; nt++)
                    MMA16816(acc[mt][nt], Ar[mt], Br[nt >> 1][(nt & 1) * 2],
                             Br[nt >> 1][(nt & 1) * 2 + 1]);
        }
    }

    float b0r[4], b1r[4];
#pragma unroll
    for (int nt = 0; nt < 4; nt++) {
        b0r[nt] = b2s[wn * 32 + nt * 8 + tig * 2];
        b1r[nt] = b2s[wn * 32 + nt * 8 + tig * 2 + 1];
    }
#pragma unroll
    for (int mt = 0; mt < 4; mt++) {
        int rA = row0 + wm * 64 + mt * 16 + g;
        int rB = rA + 8;
#pragma unroll
        for (int nt = 0; nt < 4; nt++) {
            int e = e0 + wn * 32 + nt * 8 + tig * 2;
            float2 vA = make_float2(ftanh(acc[mt][nt][0] + b0r[nt]),
                                    ftanh(acc[mt][nt][1] + b1r[nt]));
            float2 vB = make_float2(ftanh(acc[mt][nt][2] + b0r[nt]),
                                    ftanh(acc[mt][nt][3] + b1r[nt]));
            *(float2*)&g_x2[(size_t)rA * EE + e] = vA;
            *(float2*)&g_x2[(size_t)rB * EE + e] = vB;
        }
    }
}

// ---------------------------------------------------------------------------
// K2 (PERSISTENT): R14 inner loop verbatim, but one CTA per SM loops over
// tiles.  W1 + b1 loaded ONCE per CTA (L2 W1 traffic 400MB -> 19MB, kills
// the ~3K-cycle per-wave prologue).  Cross-tile A prefetch at kc==7 keeps
// the LDG pipeline full across tile boundaries.
// ---------------------------------------------------------------------------
#define OFF_B1  0
#define OFF_X2  1024
#define OFF_BW  5248
#define OFF_A   140416
#define A_BUF   10240
#define K2_SMEM 160896

__global__ __launch_bounds__(256, 1) void k2_scores(const float* __restrict__ X,
                                                    const float* __restrict__ b1) {
    extern __shared__ __align__(16) char smem[];
    float* b1s = (float*)(smem + OFF_B1);
    float* x2s = (float*)(smem + OFF_X2);

    const int tid = threadIdx.x;
    const int w = tid >> 5, lane = tid & 31;
    const int tig = lane & 3, g = lane >> 2;
    const int wm = w >> 2, wn = w & 3;

    // ---- one-time: W1 (fp16) -> padded smem, b1 -> smem ----
    {
        const uint4* Wp = (const uint4*)g_w1h;
        for (int i = tid; i < 8192; i += 256) {
            int r = i >> 5, s2 = i & 31;
            *(uint4*)(smem + OFF_BW + r * 528 + s2 * 16) = Wp[i];
        }
    }
    if (tid < EE) b1s[tid] = b1[tid];

    const uint32_t sb = smem_u32(smem);
    const int arow = lane & 15, asel = lane >> 4;
    const uint32_t aAddr0 = sb + OFF_A + (uint32_t)(wm * 64 + arow) * 80 + asel * 16;
    const int brow = (lane & 7) + ((lane >> 4) << 3), bsel = (lane >> 3) & 1;
    const uint32_t bAddr0 = sb + OFF_BW + (uint32_t)(wn * 64 + brow) * 528 + bsel * 16;
    char* stsP = smem + OFF_A + (tid >> 1) * 80 + (tid & 1) * 32;

    // per-thread A base: row (tid>>1), 16-float half (tid&1)
    const float* XpBase = X + (size_t)(tid >> 1) * FF + (tid & 1) * 16;
    const int G = gridDim.x;

    // prefetch chunk 0 of first tile
    const float* Xp = XpBase + (size_t)blockIdx.x * 128 * FF;
    float4 pr0 = *(const float4*)(Xp + 0);
    float4 pr1 = *(const float4*)(Xp + 4);
    float4 pr2 = *(const float4*)(Xp + 8);
    float4 pr3 = *(const float4*)(Xp + 12);

    const float inv = 1.f / (float)PP;

    for (int t = blockIdx.x; t < NTILES; t += G) {
        const int row0 = t * 128;
        const int n0 = row0 / PP;
        const float* XpCur = XpBase + (size_t)row0 * FF;
        const float* XpNext = XpBase + ((size_t)row0 + (size_t)G * 128) * FF;
        const bool hasNext = (t + G) < NTILES;

        // x2 slice for this tile (x2s protected by loop-end barrier)
        for (int i = tid; i < 4 * EE; i += 256) {
            int s = i >> 8, e = i & 255;
            int n = n0 + s;
            x2s[s * 260 + e] = (n < NN) ? g_x2[(size_t)n * EE + e] : 0.f;
        }

        float acc[4][8][4];
#pragma unroll
        for (int mt = 0; mt < 4; mt++)
#pragma unroll
            for (int nt = 0; nt < 8; nt++)
#pragma unroll
                for (int i = 0; i < 4; i++) acc[mt][nt][i] = 0.f;

        for (int kc = 0; kc < 8; kc++) {
            const uint32_t bo = (kc & 1) * A_BUF;
            {
                uint4 q0, q1;
                q0.x = pack_h2(pr0.x, pr0.y); q0.y = pack_h2(pr0.z, pr0.w);
                q0.z = pack_h2(pr1.x, pr1.y); q0.w = pack_h2(pr1.z, pr1.w);
                q1.x = pack_h2(pr2.x, pr2.y); q1.y = pack_h2(pr2.z, pr2.w);
                q1.z = pack_h2(pr3.x, pr3.y); q1.w = pack_h2(pr3.z, pr3.w);
                *(uint4*)(stsP + bo) = q0;
                *(uint4*)(stsP + bo + 16) = q1;
            }
            __syncthreads();
            if (kc < 7) {
                const float* Xn = XpCur + (kc + 1) * 32;
                pr0 = *(const float4*)(Xn + 0);
                pr1 = *(const float4*)(Xn + 4);
                pr2 = *(const float4*)(Xn + 8);
                pr3 = *(const float4*)(Xn + 12);
            } else if (hasNext) {
                // cross-tile prefetch: chunk 0 of tile t+G (into buf 0 next iter;
                // buf 0's last reads finished before the kc==7 barrier above)
                pr0 = *(const float4*)(XpNext + 0);
                pr1 = *(const float4*)(XpNext + 4);
                pr2 = *(const float4*)(XpNext + 8);
                pr3 = *(const float4*)(XpNext + 12);
            }
#pragma unroll
            for (int ks = 0; ks < 2; ks++) {
                uint32_t Ar[4][4], Br[4][4];
#pragma unroll
                for (int mt = 0; mt < 4; mt++)
                    LDSM4(Ar[mt], aAddr0 + bo + mt * (16 * 80) + ks * 32);
#pragma unroll
                for (int np = 0; np < 4; np++)
                    LDSM4(Br[np], bAddr0 + np * (16 * 528) + kc * 64 + ks * 32);
#pragma unroll
                for (int mt = 0; mt < 4; mt++)
#pragma unroll
                    for (int nt = 0; nt < 8; nt++)
                        MMA16816(acc[mt][nt], Ar[mt], Br[nt >> 1][(nt & 1) * 2],
                                 Br[nt >> 1][(nt & 1) * 2 + 1]);
            }
        }

        // ---- epilogue: tanh.approx + dot(x2) + quad shuffle + atomicAdd ----
#pragma unroll
        for (int mt = 0; mt < 4; mt++) {
            int rA = wm * 64 + mt * 16 + g;
            int rB = rA + 8;
            int nA = (row0 + rA) / PP;
            int nB = (row0 + rB) / PP;
            const float* xA = x2s + (nA - n0) * 260 + wn * 64;
            const float* xB = x2s + (nB - n0) * 260 + wn * 64;
            float sA = 0.f, sB = 0.f;
#pragma unroll
            for (int nt = 0; nt < 8; nt++) {
                int c0 = nt * 8 + tig * 2, c1 = c0 + 1;
                float bb0 = b1s[wn * 64 + c0];
                float bb1 = b1s[wn * 64 + c1];
                sA += tanha(acc[mt][nt][0] + bb0) * xA[c0]
                    + tanha(acc[mt][nt][1] + bb1) * xA[c1];
                sB += tanha(acc[mt][nt][2] + bb0) * xB[c0]
                    + tanha(acc[mt][nt][3] + bb1) * xB[c1];
            }
            sA += __shfl_xor_sync(0xffffffffu, sA, 1);
            sA += __shfl_xor_sync(0xffffffffu, sA, 2);
            sB += __shfl_xor_sync(0xffffffffu, sB, 1);
            sB += __shfl_xor_sync(0xffffffffu, sB, 2);
            if (tig == 0) {
                atomicAdd(&g_scores[nA], sA * inv);
                atomicAdd(&g_scores[nB], sB * inv);
            }
        }
        __syncthreads();   // protect x2s before next tile's overwrite
    }
}

// ---------------------------------------------------------------------------
// K3: per-segment softmax over scalar scores (patch_lens int32 or int64).
// ---------------------------------------------------------------------------
__device__ __forceinline__ int seg_len(const int* p32, int is64, int i) {
    return is64 ? p32[2 * i] : p32[i];
}

__global__ __launch_bounds__(128) void k3_softmax(const int* __restrict__ lens32) {
    __shared__ float sh[128];
    __shared__ int s_off, s_len;
    int s = blockIdx.x, tid = threadIdx.x;
    if (tid == 0) {
        int is64 = (lens32[1] == 0) ? 1 : 0;
        int o = 0;
        for (int i = 0; i < s; i++) o += seg_len(lens32, is64, i);
        s_off = o;
        s_len = seg_len(lens32, is64, s);
    }
    __syncthreads();
    int off = s_off, len = s_len;
    float v = (tid < len) ? g_scores[off + tid] : -1e30f;
    sh[tid] = v;
    __syncthreads();
    for (int st = 64; st > 0; st >>= 1) {
        if (tid < st) sh[tid] = fmaxf(sh[tid], sh[tid + st]);
        __syncthreads();
    }
    float m = sh[0];
    __syncthreads();
    float e = (tid < len) ? expf(v - m) : 0.f;
    sh[tid] = e;
    __syncthreads();
    for (int st = 64; st > 0; st >>= 1) {
        if (tid < st) sh[tid] += sh[tid + st];
        __syncthreads();
    }
    float z = sh[0];
    if (tid < len) g_attn[off + tid] = e / z;
}

// ---------------------------------------------------------------------------
// K4: out[n,f] = attn[n] * sum_p x[n,p,f]   (R4-proven, ~82% DRAM peak)
// ---------------------------------------------------------------------------
__global__ __launch_bounds__(256) void k4_out(const float* __restrict__ X,
                                              float* __restrict__ out) {
    int n = blockIdx.x, f = threadIdx.x;
    const float* xp = X + (size_t)n * PP * FF + f;
    float acc = 0.f;
#pragma unroll
    for (int p = 0; p < PP; p++) acc += xp[(size_t)p * FF];
    out[(size_t)n * FF + f] = acc * g_attn[n];
}

// ---------------------------------------------------------------------------
extern "C" void kernel_launch(void* const* d_in, const int* in_sizes, int n_in,
                              void* d_out, int out_size) {
    const float* x      = (const float*)d_in[0];
    const float* hidden = (const float*)d_in[1];
    const float* W1     = (const float*)d_in[2];
    const float* b1     = (const float*)d_in[3];
    const float* W2     = (const float*)d_in[4];
    const float* b2     = (const float*)d_in[5];
    const int* pl       = (const int*)d_in[6];

    float* out = (float*)d_out;

    static bool s_init = false;
    static int s_nsm = 148;
    if (!s_init) {
        cudaFuncSetAttribute(k2_scores, cudaFuncAttributeMaxDynamicSharedMemorySize, K2_SMEM);
        cudaFuncSetAttribute(k1m_x2, cudaFuncAttributeMaxDynamicSharedMemorySize, K1M_SMEM);
        int dev = 0, nsm = 0;
        cudaGetDevice(&dev);
        if (cudaDeviceGetAttribute(&nsm, cudaDevAttrMultiProcessorCount, dev) == cudaSuccess && nsm > 0)
            s_nsm = nsm;   // persistent grid = exactly one CTA per SM
        s_init = true;
    }

    // fully serial, default stream; k2 at launch slot 4 (ncu capture)
    k0_prep<<<256, 256>>>(W1, W2);
    kdummy<<<1, 32>>>();
    k1m_x2<<<dim3(64, 2), 256, K1M_SMEM>>>(hidden, b2);
    k2_scores<<<s_nsm, 256, K2_SMEM>>>(x, b1);
    k3_softmax<<<SS, 128>>>(pl);
    k4_out<<<NN, 256>>>(x, out);
}